// round 1
// baseline (speedup 1.0000x reference)
#include <cuda_runtime.h>
#include <cuda_bf16.h>

#define NPTS 4096
#define NF   (NPTS - 2)
#define EPSF 1e-8f
#define LOSS_BLOCKS  592
#define LOSS_THREADS 256

// Scratch (device globals only — no allocations allowed)
__device__ float g_px[NPTS], g_py[NPTS], g_pz[NPTS];
__device__ float g_tx[NPTS], g_ty[NPTS], g_tz[NPTS];
__device__ float g_pf[NF][12];   // pred frames: origin(3) + e1,e2,e3 rows (9)
__device__ float g_tf[NF][12];   // true frames
__device__ double g_acc;

__device__ __forceinline__ float fsqrt_fast(float x) {
    float y;
    asm("sqrt.approx.f32 %0, %1;" : "=f"(y) : "f"(x));
    return y;
}

__device__ __forceinline__ void make_frame(const float* __restrict__ c, int i, float* __restrict__ fr) {
    // origin = c[i+1]
    float ox = c[3 * i + 3], oy = c[3 * i + 4], oz = c[3 * i + 5];
    // e1 = c[i+2] - c[i+1], normalized by (norm + EPS)
    float e1x = c[3 * i + 6] - ox, e1y = c[3 * i + 7] - oy, e1z = c[3 * i + 8] - oz;
    float n1 = fsqrt_fast(e1x * e1x + e1y * e1y + e1z * e1z);
    float inv1 = 1.0f / (n1 + EPSF);
    e1x *= inv1; e1y *= inv1; e1z *= inv1;
    // e2 = c[i] - c[i+1], Gram-Schmidt vs e1, normalized
    float e2x = c[3 * i] - ox, e2y = c[3 * i + 1] - oy, e2z = c[3 * i + 2] - oz;
    float d = e2x * e1x + e2y * e1y + e2z * e1z;
    e2x -= d * e1x; e2y -= d * e1y; e2z -= d * e1z;
    float n2 = fsqrt_fast(e2x * e2x + e2y * e2y + e2z * e2z);
    float inv2 = 1.0f / (n2 + EPSF);
    e2x *= inv2; e2y *= inv2; e2z *= inv2;
    // e3 = e1 x e2
    float e3x = e1y * e2z - e1z * e2y;
    float e3y = e1z * e2x - e1x * e2z;
    float e3z = e1x * e2y - e1y * e2x;
    fr[0] = ox;  fr[1] = oy;  fr[2] = oz;
    fr[3] = e1x; fr[4] = e1y; fr[5] = e1z;
    fr[6] = e2x; fr[7] = e2y; fr[8] = e2z;
    fr[9] = e3x; fr[10] = e3y; fr[11] = e3z;
}

// Kernel 1: zero accumulator, transpose coords to SoA, build all frames.
__global__ void prep_kernel(const float* __restrict__ pred, const float* __restrict__ truec) {
    int i = blockIdx.x * blockDim.x + threadIdx.x;
    if (i == 0) g_acc = 0.0;
    if (i < NPTS) {
        g_px[i] = pred[3 * i];  g_py[i] = pred[3 * i + 1];  g_pz[i] = pred[3 * i + 2];
        g_tx[i] = truec[3 * i]; g_ty[i] = truec[3 * i + 1]; g_tz[i] = truec[3 * i + 2];
    }
    if (i < NF) {
        make_frame(pred, i, g_pf[i]);
        make_frame(truec, i, g_tf[i]);
    }
}

// Kernel 2: main FAPE loop. Each block handles a strided set of frames; all
// threads sweep the N points. Frames live in registers across the point loop.
__global__ void __launch_bounds__(LOSS_THREADS) loss_kernel() {
    float sum = 0.0f;

    for (int f = blockIdx.x; f < NF; f += LOSS_BLOCKS) {
        const float* __restrict__ pf = g_pf[f];
        const float* __restrict__ tf = g_tf[f];
        float pox = pf[0], poy = pf[1], poz = pf[2];
        float p00 = pf[3], p01 = pf[4], p02 = pf[5];
        float p10 = pf[6], p11 = pf[7], p12 = pf[8];
        float p20 = pf[9], p21 = pf[10], p22 = pf[11];
        float tox = tf[0], toy = tf[1], toz = tf[2];
        float t00 = tf[3], t01 = tf[4], t02 = tf[5];
        float t10 = tf[6], t11 = tf[7], t12 = tf[8];
        float t20 = tf[9], t21 = tf[10], t22 = tf[11];

        #pragma unroll 4
        for (int n = threadIdx.x; n < NPTS; n += LOSS_THREADS) {
            float px = g_px[n], py = g_py[n], pz = g_pz[n];
            float cx = px - pox, cy = py - poy, cz = pz - poz;
            float plx = cx * p00 + cy * p01 + cz * p02;
            float ply = cx * p10 + cy * p11 + cz * p12;
            float plz = cx * p20 + cy * p21 + cz * p22;

            float qx = g_tx[n], qy = g_ty[n], qz = g_tz[n];
            float ux = qx - tox, uy = qy - toy, uz = qz - toz;
            float tlx = ux * t00 + uy * t01 + uz * t02;
            float tly = ux * t10 + uy * t11 + uz * t12;
            float tlz = ux * t20 + uy * t21 + uz * t22;

            float dx = plx - tlx, dy = ply - tly, dz = plz - tlz;
            float ss = dx * dx + dy * dy + dz * dz + EPSF;
            float dist = fsqrt_fast(ss);
            sum += fminf(dist, 10.0f);
        }
    }

    // warp reduce
    #pragma unroll
    for (int o = 16; o > 0; o >>= 1)
        sum += __shfl_down_sync(0xffffffffu, sum, o);

    __shared__ float wsum[LOSS_THREADS / 32];
    int lane = threadIdx.x & 31;
    int wid  = threadIdx.x >> 5;
    if (lane == 0) wsum[wid] = sum;
    __syncthreads();
    if (wid == 0) {
        float v = (lane < LOSS_THREADS / 32) ? wsum[lane] : 0.0f;
        #pragma unroll
        for (int o = 4; o > 0; o >>= 1)
            v += __shfl_down_sync(0xffffffffu, v, o);
        if (lane == 0) atomicAdd(&g_acc, (double)v);
    }
}

// Kernel 3: finalize — mean over F*N, divide by LOSS_UNIT_DISTANCE.
__global__ void fin_kernel(float* __restrict__ out) {
    out[0] = (float)(g_acc / ((double)NF * (double)NPTS) / 10.0);
}

extern "C" void kernel_launch(void* const* d_in, const int* in_sizes, int n_in,
                              void* d_out, int out_size) {
    const float* pred  = (const float*)d_in[0];
    const float* truec = (const float*)d_in[1];
    float* out = (float*)d_out;

    prep_kernel<<<(NPTS + 255) / 256, 256>>>(pred, truec);
    loss_kernel<<<LOSS_BLOCKS, LOSS_THREADS>>>();
    fin_kernel<<<1, 1>>>(out);
}

// round 2
// speedup vs baseline: 1.1712x; 1.1712x over previous
#include <cuda_runtime.h>
#include <cuda_bf16.h>

#define NPTS 4096
#define NF   (NPTS - 2)
#define EPSF 1e-8f
#define LT   256
#define LB   592

typedef unsigned long long u64;

// Scratch (device globals only — allocations are forbidden)
__device__ __align__(16) float g_px[NPTS], g_py[NPTS], g_pz[NPTS];
__device__ __align__(16) float g_qx[NPTS], g_qy[NPTS], g_qz[NPTS];
// Per-frame fused constants, lane-replicated for f32x2 math:
// [0..8]=Rp rows, [9..17]=-Rt rows, [18..20]=c = Rt*ot - Rp*op
__device__ u64 g_fr[NF][21];
__device__ double g_acc;

__device__ __forceinline__ float rsqrt_fast(float x) {
    float y; asm("rsqrt.approx.f32 %0, %1;" : "=f"(y) : "f"(x)); return y;
}
__device__ __forceinline__ float sqrt_fast(float x) {
    float y; asm("sqrt.approx.f32 %0, %1;" : "=f"(y) : "f"(x)); return y;
}
__device__ __forceinline__ u64 dupf(float a) {
    u64 r; asm("mov.b64 %0, {%1, %1};" : "=l"(r) : "f"(a)); return r;
}
__device__ __forceinline__ u64 ffma2(u64 a, u64 b, u64 c) {
    u64 d; asm("fma.rn.f32x2 %0, %1, %2, %3;" : "=l"(d) : "l"(a), "l"(b), "l"(c));
    return d;
}
__device__ __forceinline__ void unpk(u64 v, float& lo, float& hi) {
    asm("mov.b64 {%0, %1}, %2;" : "=f"(lo), "=f"(hi) : "l"(v));
}

// Build rigid frame i from AoS coords: R rows e1,e2,e3 and origin o.
__device__ __forceinline__ void build_frame(const float* __restrict__ c, int i,
                                            float* __restrict__ R, float* __restrict__ o) {
    float ox = c[3*i+3], oy = c[3*i+4], oz = c[3*i+5];
    float ax = c[3*i+6] - ox, ay = c[3*i+7] - oy, az = c[3*i+8] - oz;
    float i1 = rsqrt_fast(ax*ax + ay*ay + az*az);
    ax *= i1; ay *= i1; az *= i1;
    float bx = c[3*i] - ox, by = c[3*i+1] - oy, bz = c[3*i+2] - oz;
    float d = bx*ax + by*ay + bz*az;
    bx -= d*ax; by -= d*ay; bz -= d*az;
    float i2 = rsqrt_fast(bx*bx + by*by + bz*bz);
    bx *= i2; by *= i2; bz *= i2;
    float cx = ay*bz - az*by;
    float cy = az*bx - ax*bz;
    float cz = ax*by - ay*bx;
    R[0]=ax; R[1]=ay; R[2]=az;
    R[3]=bx; R[4]=by; R[5]=bz;
    R[6]=cx; R[7]=cy; R[8]=cz;
    o[0]=ox; o[1]=oy; o[2]=oz;
}

__global__ void prep_kernel(const float* __restrict__ pred, const float* __restrict__ tru) {
    int i = blockIdx.x * blockDim.x + threadIdx.x;
    if (i == 0) g_acc = 0.0;
    if (i < NPTS) {
        g_px[i] = pred[3*i]; g_py[i] = pred[3*i+1]; g_pz[i] = pred[3*i+2];
        g_qx[i] = tru[3*i];  g_qy[i] = tru[3*i+1];  g_qz[i] = tru[3*i+2];
    }
    if (i < NF) {
        float Rp[9], op[3], Rt[9], ot[3];
        build_frame(pred, i, Rp, op);
        build_frame(tru,  i, Rt, ot);
        u64* fr = g_fr[i];
        #pragma unroll
        for (int k = 0; k < 9; k++) fr[k]     = dupf(Rp[k]);
        #pragma unroll
        for (int k = 0; k < 9; k++) fr[9 + k] = dupf(-Rt[k]);
        #pragma unroll
        for (int r = 0; r < 3; r++) {
            float cc = (Rt[3*r]*ot[0] + Rt[3*r+1]*ot[1] + Rt[3*r+2]*ot[2])
                     - (Rp[3*r]*op[0] + Rp[3*r+1]*op[1] + Rp[3*r+2]*op[2]);
            fr[18 + r] = dupf(cc);
        }
    }
}

__global__ void __launch_bounds__(LT) loss_kernel() {
    const u64* PX = (const u64*)g_px;
    const u64* PY = (const u64*)g_py;
    const u64* PZ = (const u64*)g_pz;
    const u64* QX = (const u64*)g_qx;
    const u64* QY = (const u64*)g_qy;
    const u64* QZ = (const u64*)g_qz;

    const u64 eps2 = dupf(EPSF);
    float s0 = 0.0f, s1 = 0.0f;

    for (int f = blockIdx.x; f < NF; f += LB) {
        const u64* __restrict__ fr = g_fr[f];
        u64 m00 = fr[0],  m01 = fr[1],  m02 = fr[2];
        u64 m10 = fr[3],  m11 = fr[4],  m12 = fr[5];
        u64 m20 = fr[6],  m21 = fr[7],  m22 = fr[8];
        u64 n00 = fr[9],  n01 = fr[10], n02 = fr[11];
        u64 n10 = fr[12], n11 = fr[13], n12 = fr[14];
        u64 n20 = fr[15], n21 = fr[16], n22 = fr[17];
        u64 c0  = fr[18], c1  = fr[19], c2  = fr[20];

        #pragma unroll 2
        for (int h = threadIdx.x; h < NPTS / 2; h += LT) {
            u64 px = PX[h], py = PY[h], pz = PZ[h];
            u64 qx = QX[h], qy = QY[h], qz = QZ[h];

            u64 dx = ffma2(m00, px, ffma2(m01, py, ffma2(m02, pz,
                     ffma2(n00, qx, ffma2(n01, qy, ffma2(n02, qz, c0))))));
            u64 dy = ffma2(m10, px, ffma2(m11, py, ffma2(m12, pz,
                     ffma2(n10, qx, ffma2(n11, qy, ffma2(n12, qz, c1))))));
            u64 dz = ffma2(m20, px, ffma2(m21, py, ffma2(m22, pz,
                     ffma2(n20, qx, ffma2(n21, qy, ffma2(n22, qz, c2))))));

            u64 ss = ffma2(dx, dx, ffma2(dy, dy, ffma2(dz, dz, eps2)));
            float a, b; unpk(ss, a, b);
            s0 += fminf(sqrt_fast(a), 10.0f);
            s1 += fminf(sqrt_fast(b), 10.0f);
        }
    }

    float sum = s0 + s1;
    #pragma unroll
    for (int o = 16; o > 0; o >>= 1)
        sum += __shfl_down_sync(0xffffffffu, sum, o);

    __shared__ float wsum[LT / 32];
    int lane = threadIdx.x & 31;
    int wid  = threadIdx.x >> 5;
    if (lane == 0) wsum[wid] = sum;
    __syncthreads();
    if (wid == 0) {
        float v = (lane < LT / 32) ? wsum[lane] : 0.0f;
        #pragma unroll
        for (int o = 4; o > 0; o >>= 1)
            v += __shfl_down_sync(0xffffffffu, v, o);
        if (lane == 0) atomicAdd(&g_acc, (double)v);
    }
}

__global__ void fin_kernel(float* __restrict__ out) {
    out[0] = (float)(g_acc / ((double)NF * (double)NPTS) / 10.0);
}

extern "C" void kernel_launch(void* const* d_in, const int* in_sizes, int n_in,
                              void* d_out, int out_size) {
    const float* pred = (const float*)d_in[0];
    const float* tru  = (const float*)d_in[1];
    float* out = (float*)d_out;

    prep_kernel<<<(NPTS + 255) / 256, 256>>>(pred, tru);
    loss_kernel<<<LB, LT>>>();
    fin_kernel<<<1, 1>>>(out);
}

// round 3
// speedup vs baseline: 1.3931x; 1.1894x over previous
#include <cuda_runtime.h>
#include <cuda_bf16.h>

#define NPTS 4096
#define NF   (NPTS - 2)
#define EPSF 1e-8f
#define LT   256
#define NCHUNK (NPTS / 4)   // 1024 blocks, 4 frames each (incl. 2 pad frames)

typedef unsigned long long u64;

// Scratch (device globals only — allocations forbidden)
__device__ __align__(16) float g_px[NPTS], g_py[NPTS], g_pz[NPTS];
__device__ __align__(16) float g_qx[NPTS], g_qy[NPTS], g_qz[NPTS];
// Frame constants, SoA over frames (padded to 4096):
// k=0..8: Rp rows, k=9..17: -Rt rows, k=18..20: c = Rt*ot - Rp*op
__device__ __align__(16) float g_fc[21][NPTS];
__device__ double g_acc;
__device__ unsigned g_tick;

__device__ __forceinline__ float rsqrt_fast(float x) {
    float y; asm("rsqrt.approx.f32 %0, %1;" : "=f"(y) : "f"(x)); return y;
}
__device__ __forceinline__ float sqrt_fast(float x) {
    float y; asm("sqrt.approx.f32 %0, %1;" : "=f"(y) : "f"(x)); return y;
}
__device__ __forceinline__ u64 dupf(float a) {
    u64 r; asm("mov.b64 %0, {%1, %1};" : "=l"(r) : "f"(a)); return r;
}
__device__ __forceinline__ u64 ffma2(u64 a, u64 b, u64 c) {
    u64 d; asm("fma.rn.f32x2 %0, %1, %2, %3;" : "=l"(d) : "l"(a), "l"(b), "l"(c));
    return d;
}
__device__ __forceinline__ void unpk(u64 v, float& lo, float& hi) {
    asm("mov.b64 {%0, %1}, %2;" : "=f"(lo), "=f"(hi) : "l"(v));
}

__device__ __forceinline__ void build_frame(const float* __restrict__ c, int i,
                                            float* __restrict__ R, float* __restrict__ o) {
    float ox = c[3*i+3], oy = c[3*i+4], oz = c[3*i+5];
    float ax = c[3*i+6] - ox, ay = c[3*i+7] - oy, az = c[3*i+8] - oz;
    float i1 = rsqrt_fast(ax*ax + ay*ay + az*az);
    ax *= i1; ay *= i1; az *= i1;
    float bx = c[3*i] - ox, by = c[3*i+1] - oy, bz = c[3*i+2] - oz;
    float d = bx*ax + by*ay + bz*az;
    bx -= d*ax; by -= d*ay; bz -= d*az;
    float i2 = rsqrt_fast(bx*bx + by*by + bz*bz);
    bx *= i2; by *= i2; bz *= i2;
    R[0]=ax; R[1]=ay; R[2]=az;
    R[3]=bx; R[4]=by; R[5]=bz;
    R[6]=ay*bz - az*by; R[7]=az*bx - ax*bz; R[8]=ax*by - ay*bx;
    o[0]=ox; o[1]=oy; o[2]=oz;
}

__global__ void prep_kernel(const float* __restrict__ pred, const float* __restrict__ tru) {
    int i = blockIdx.x * blockDim.x + threadIdx.x;
    if (i == 0) g_acc = 0.0;
    if (i < NPTS) {
        g_px[i] = pred[3*i]; g_py[i] = pred[3*i+1]; g_pz[i] = pred[3*i+2];
        g_qx[i] = tru[3*i];  g_qy[i] = tru[3*i+1];  g_qz[i] = tru[3*i+2];
    }
    if (i < NF) {
        float Rp[9], op[3], Rt[9], ot[3];
        build_frame(pred, i, Rp, op);
        build_frame(tru,  i, Rt, ot);
        #pragma unroll
        for (int k = 0; k < 9; k++) g_fc[k][i]     = Rp[k];
        #pragma unroll
        for (int k = 0; k < 9; k++) g_fc[9 + k][i] = -Rt[k];
        #pragma unroll
        for (int r = 0; r < 3; r++) {
            g_fc[18 + r][i] = (Rt[3*r]*ot[0] + Rt[3*r+1]*ot[1] + Rt[3*r+2]*ot[2])
                            - (Rp[3*r]*op[0] + Rp[3*r+1]*op[1] + Rp[3*r+2]*op[2]);
        }
    } else if (i < NPTS) {
        // Pad frames: dist clamps to exactly 10.0, subtracted analytically later.
        #pragma unroll
        for (int k = 0; k < 21; k++) g_fc[k][i] = 0.0f;
        g_fc[18][i] = 1e6f;
    }
}

// Each block: 4 frames (two f32x2 frame-pairs), all 4096 points.
__global__ void __launch_bounds__(LT) loss_kernel(float* __restrict__ out) {
    const int f = blockIdx.x * 4;

    u64 A[21], B[21];
    #pragma unroll
    for (int k = 0; k < 21; k++) {
        A[k] = *(const u64*)&g_fc[k][f];
        B[k] = *(const u64*)&g_fc[k][f + 2];
    }
    const u64 eps2 = dupf(EPSF);

    float s0 = 0.0f, s1 = 0.0f, s2 = 0.0f, s3 = 0.0f;

    #pragma unroll 2
    for (int n = threadIdx.x; n < NPTS; n += LT) {
        u64 X = dupf(g_px[n]), Y = dupf(g_py[n]), Z = dupf(g_pz[n]);
        u64 U = dupf(g_qx[n]), V = dupf(g_qy[n]), W = dupf(g_qz[n]);

        u64 ax = ffma2(A[0], X, ffma2(A[1], Y, ffma2(A[2], Z,
                 ffma2(A[9], U, ffma2(A[10], V, ffma2(A[11], W, A[18]))))));
        u64 ay = ffma2(A[3], X, ffma2(A[4], Y, ffma2(A[5], Z,
                 ffma2(A[12], U, ffma2(A[13], V, ffma2(A[14], W, A[19]))))));
        u64 az = ffma2(A[6], X, ffma2(A[7], Y, ffma2(A[8], Z,
                 ffma2(A[15], U, ffma2(A[16], V, ffma2(A[17], W, A[20]))))));

        u64 bx = ffma2(B[0], X, ffma2(B[1], Y, ffma2(B[2], Z,
                 ffma2(B[9], U, ffma2(B[10], V, ffma2(B[11], W, B[18]))))));
        u64 by = ffma2(B[3], X, ffma2(B[4], Y, ffma2(B[5], Z,
                 ffma2(B[12], U, ffma2(B[13], V, ffma2(B[14], W, B[19]))))));
        u64 bz = ffma2(B[6], X, ffma2(B[7], Y, ffma2(B[8], Z,
                 ffma2(B[15], U, ffma2(B[16], V, ffma2(B[17], W, B[20]))))));

        u64 ssa = ffma2(ax, ax, ffma2(ay, ay, ffma2(az, az, eps2)));
        u64 ssb = ffma2(bx, bx, ffma2(by, by, ffma2(bz, bz, eps2)));

        float v0, v1, v2, v3;
        unpk(ssa, v0, v1);
        unpk(ssb, v2, v3);
        s0 += fminf(sqrt_fast(v0), 10.0f);
        s1 += fminf(sqrt_fast(v1), 10.0f);
        s2 += fminf(sqrt_fast(v2), 10.0f);
        s3 += fminf(sqrt_fast(v3), 10.0f);
    }

    float sum = (s0 + s1) + (s2 + s3);
    #pragma unroll
    for (int o = 16; o > 0; o >>= 1)
        sum += __shfl_down_sync(0xffffffffu, sum, o);

    __shared__ float wsum[LT / 32];
    int lane = threadIdx.x & 31;
    int wid  = threadIdx.x >> 5;
    if (lane == 0) wsum[wid] = sum;
    __syncthreads();
    if (threadIdx.x == 0) {
        float v = 0.0f;
        #pragma unroll
        for (int w = 0; w < LT / 32; w++) v += wsum[w];
        atomicAdd(&g_acc, (double)v);
        __threadfence();
        unsigned t = atomicAdd(&g_tick, 1u);
        if (t == (unsigned)(gridDim.x - 1)) {
            double total = *((volatile double*)&g_acc);
            total -= 2.0 * (double)NPTS * 10.0;   // remove pad-frame contribution (exactly 10 each)
            out[0] = (float)(total / ((double)NF * (double)NPTS) / 10.0);
            g_tick = 0u;  // reset for next graph replay
        }
    }
}

extern "C" void kernel_launch(void* const* d_in, const int* in_sizes, int n_in,
                              void* d_out, int out_size) {
    const float* pred = (const float*)d_in[0];
    const float* tru  = (const float*)d_in[1];
    float* out = (float*)d_out;

    prep_kernel<<<(NPTS + 255) / 256, 256>>>(pred, tru);
    loss_kernel<<<NCHUNK, LT>>>(out);
}

// round 4
// speedup vs baseline: 1.5000x; 1.0768x over previous
#include <cuda_runtime.h>
#include <cuda_bf16.h>

#define NPTS 4096
#define NF   (NPTS - 2)
#define EPSF 1e-8f
#define LT   256
#define NBLK (NPTS / 2)      // 2048 blocks: 4 frames x 2048 points each

typedef unsigned long long u64;

// Scratch (device globals only — allocations forbidden)
__device__ __align__(16) float g_px[NPTS], g_py[NPTS], g_pz[NPTS];
__device__ __align__(16) float g_qx[NPTS], g_qy[NPTS], g_qz[NPTS];
// Fused frame constants, SoA over frames (padded to 4096):
// k=0..8: M = Rp^T * Rt (row-major), k=9..11: c = op - M*ot
__device__ __align__(16) float g_fc[12][NPTS];
__device__ double g_acc;
__device__ unsigned g_tick;

__device__ __forceinline__ float rsqrt_fast(float x) {
    float y; asm("rsqrt.approx.f32 %0, %1;" : "=f"(y) : "f"(x)); return y;
}
__device__ __forceinline__ float sqrt_fast(float x) {
    float y; asm("sqrt.approx.f32 %0, %1;" : "=f"(y) : "f"(x)); return y;
}
__device__ __forceinline__ u64 dupf(float a) {
    u64 r; asm("mov.b64 %0, {%1, %1};" : "=l"(r) : "f"(a)); return r;
}
__device__ __forceinline__ u64 ffma2(u64 a, u64 b, u64 c) {
    u64 d; asm("fma.rn.f32x2 %0, %1, %2, %3;" : "=l"(d) : "l"(a), "l"(b), "l"(c));
    return d;
}
__device__ __forceinline__ u64 fadd2(u64 a, u64 b) {
    u64 d; asm("add.rn.f32x2 %0, %1, %2;" : "=l"(d) : "l"(a), "l"(b));
    return d;
}
__device__ __forceinline__ void unpk(u64 v, float& lo, float& hi) {
    asm("mov.b64 {%0, %1}, %2;" : "=f"(lo), "=f"(hi) : "l"(v));
}
__device__ __forceinline__ float fneg_bits(float x) {
    return __int_as_float(__float_as_int(x) ^ 0x80000000);
}

__device__ __forceinline__ void build_frame(const float* __restrict__ c, int i,
                                            float* __restrict__ R, float* __restrict__ o) {
    float ox = c[3*i+3], oy = c[3*i+4], oz = c[3*i+5];
    float ax = c[3*i+6] - ox, ay = c[3*i+7] - oy, az = c[3*i+8] - oz;
    float i1 = rsqrt_fast(ax*ax + ay*ay + az*az);
    ax *= i1; ay *= i1; az *= i1;
    float bx = c[3*i] - ox, by = c[3*i+1] - oy, bz = c[3*i+2] - oz;
    float d = bx*ax + by*ay + bz*az;
    bx -= d*ax; by -= d*ay; bz -= d*az;
    float i2 = rsqrt_fast(bx*bx + by*by + bz*bz);
    bx *= i2; by *= i2; bz *= i2;
    R[0]=ax; R[1]=ay; R[2]=az;
    R[3]=bx; R[4]=by; R[5]=bz;
    R[6]=ay*bz - az*by; R[7]=az*bx - ax*bz; R[8]=ax*by - ay*bx;
    o[0]=ox; o[1]=oy; o[2]=oz;
}

__global__ void prep_kernel(const float* __restrict__ pred, const float* __restrict__ tru) {
    int i = blockIdx.x * blockDim.x + threadIdx.x;
    if (i == 0) g_acc = 0.0;
    if (i < NPTS) {
        g_px[i] = pred[3*i]; g_py[i] = pred[3*i+1]; g_pz[i] = pred[3*i+2];
        g_qx[i] = tru[3*i];  g_qy[i] = tru[3*i+1];  g_qz[i] = tru[3*i+2];
    }
    if (i < NF) {
        float Rp[9], op[3], Rt[9], ot[3];
        build_frame(pred, i, Rp, op);
        build_frame(tru,  i, Rt, ot);
        // M = Rp^T * Rt  (M_rc = sum_k Rp[k][r] * Rt[k][c])
        float M[9];
        #pragma unroll
        for (int r = 0; r < 3; r++)
            #pragma unroll
            for (int cc = 0; cc < 3; cc++)
                M[3*r+cc] = Rp[r]*Rt[cc] + Rp[3+r]*Rt[3+cc] + Rp[6+r]*Rt[6+cc];
        #pragma unroll
        for (int k = 0; k < 9; k++) g_fc[k][i] = M[k];
        #pragma unroll
        for (int r = 0; r < 3; r++)
            g_fc[9 + r][i] = op[r] - (M[3*r]*ot[0] + M[3*r+1]*ot[1] + M[3*r+2]*ot[2]);
    } else if (i < NPTS) {
        // Pad frames: dist clamps to exactly 10.0; removed analytically at the end.
        #pragma unroll
        for (int k = 0; k < 12; k++) g_fc[k][i] = 0.0f;
        g_fc[9][i] = 1e6f;
    }
}

// Each block: 4 frames (two f32x2 frame-pairs) x 2048 points.
__global__ void __launch_bounds__(LT, 3) loss_kernel(float* __restrict__ out) {
    const int f  = (blockIdx.x >> 1) * 4;
    const int n0 = (blockIdx.x & 1) * (NPTS / 2);

    u64 A[12], B[12];
    #pragma unroll
    for (int k = 0; k < 12; k++) {
        A[k] = *(const u64*)&g_fc[k][f];
        B[k] = *(const u64*)&g_fc[k][f + 2];
    }
    const u64 eps2 = dupf(EPSF);

    float s0 = 0.0f, s1 = 0.0f, s2 = 0.0f, s3 = 0.0f;

    #pragma unroll 2
    for (int n = n0 + threadIdx.x; n < n0 + NPTS / 2; n += LT) {
        u64 NX = dupf(fneg_bits(g_px[n]));
        u64 NY = dupf(fneg_bits(g_py[n]));
        u64 NZ = dupf(fneg_bits(g_pz[n]));
        u64 U  = dupf(g_qx[n]);
        u64 V  = dupf(g_qy[n]);
        u64 W  = dupf(g_qz[n]);

        // d = M*q + c - p   (sign of d irrelevant for |d|^2)
        u64 ax = ffma2(A[0], U, ffma2(A[1], V, ffma2(A[2], W, fadd2(A[9],  NX))));
        u64 ay = ffma2(A[3], U, ffma2(A[4], V, ffma2(A[5], W, fadd2(A[10], NY))));
        u64 az = ffma2(A[6], U, ffma2(A[7], V, ffma2(A[8], W, fadd2(A[11], NZ))));

        u64 bx = ffma2(B[0], U, ffma2(B[1], V, ffma2(B[2], W, fadd2(B[9],  NX))));
        u64 by = ffma2(B[3], U, ffma2(B[4], V, ffma2(B[5], W, fadd2(B[10], NY))));
        u64 bz = ffma2(B[6], U, ffma2(B[7], V, ffma2(B[8], W, fadd2(B[11], NZ))));

        u64 ssa = ffma2(ax, ax, ffma2(ay, ay, ffma2(az, az, eps2)));
        u64 ssb = ffma2(bx, bx, ffma2(by, by, ffma2(bz, bz, eps2)));

        float v0, v1, v2, v3;
        unpk(ssa, v0, v1);
        unpk(ssb, v2, v3);
        s0 += fminf(sqrt_fast(v0), 10.0f);
        s1 += fminf(sqrt_fast(v1), 10.0f);
        s2 += fminf(sqrt_fast(v2), 10.0f);
        s3 += fminf(sqrt_fast(v3), 10.0f);
    }

    float sum = (s0 + s1) + (s2 + s3);
    #pragma unroll
    for (int o = 16; o > 0; o >>= 1)
        sum += __shfl_down_sync(0xffffffffu, sum, o);

    __shared__ float wsum[LT / 32];
    int lane = threadIdx.x & 31;
    int wid  = threadIdx.x >> 5;
    if (lane == 0) wsum[wid] = sum;
    __syncthreads();
    if (threadIdx.x == 0) {
        float v = 0.0f;
        #pragma unroll
        for (int w = 0; w < LT / 32; w++) v += wsum[w];
        atomicAdd(&g_acc, (double)v);
        __threadfence();
        unsigned t = atomicAdd(&g_tick, 1u);
        if (t == (unsigned)(gridDim.x - 1)) {
            double total = *((volatile double*)&g_acc);
            total -= 2.0 * (double)NPTS * 10.0;   // pad frames contribute exactly 10 each
            out[0] = (float)(total / ((double)NF * (double)NPTS) / 10.0);
            g_tick = 0u;  // reset for next graph replay
        }
    }
}

extern "C" void kernel_launch(void* const* d_in, const int* in_sizes, int n_in,
                              void* d_out, int out_size) {
    const float* pred = (const float*)d_in[0];
    const float* tru  = (const float*)d_in[1];
    float* out = (float*)d_out;

    prep_kernel<<<(NPTS + 255) / 256, 256>>>(pred, tru);
    loss_kernel<<<NBLK, LT>>>(out);
}